// round 11
// baseline (speedup 1.0000x reference)
#include <cuda_runtime.h>
#include <cstdint>
#include <cstddef>
typedef unsigned long long ull;
#define C3 384

__device__ float g_xw[(size_t)1024 * 256 * C3];     // [t][b][384] gate pre-acts
__device__ float g_seq1[(size_t)1024 * 256 * 128];  // [t][b][128] layer-1 outputs

__device__ __forceinline__ ull ffma2(ull a, ull b, ull c) {
    ull d; asm("fma.rn.f32x2 %0,%1,%2,%3;" : "=l"(d) : "l"(a), "l"(b), "l"(c)); return d;
}
__device__ __forceinline__ ull pack2(float x, float y) {
    ull d; asm("mov.b64 %0,{%1,%2};" : "=l"(d) : "f"(x), "f"(y)); return d;
}
__device__ __forceinline__ float2 up2(ull v) {
    float x, y; asm("mov.b64 {%0,%1},%2;" : "=f"(x), "=f"(y) : "l"(v)); return make_float2(x, y);
}
__device__ __forceinline__ float sigm(float x) {   // 0.5*tanh(0.5x)+0.5 via HW tanh
    float t; asm("tanh.approx.f32 %0, %1;" : "=f"(t) : "f"(0.5f * x));
    return fmaf(0.5f, t, 0.5f);
}
__device__ __forceinline__ void pfL2(const void* p) {
    asm volatile("prefetch.global.L2 [%0];" :: "l"(p));
}
__device__ __forceinline__ void cpa16(void* s, const void* g) {
    uint32_t sa = (uint32_t)__cvta_generic_to_shared(s);
    asm volatile("cp.async.ca.shared.global [%0], [%1], 16;" :: "r"(sa), "l"(g));
}
__device__ __forceinline__ void cpa_commit() { asm volatile("cp.async.commit_group;"); }
__device__ __forceinline__ void cpa_wait0() { asm volatile("cp.async.wait_group 0;"); }

// ============================================================
// k_xw v5 (frozen from R10): out[t*256+b][c] = sum_k in[r][k]*W[k][c] + bias[c]
// 32-row chunks, cp.async double-buffered; thread = (col-pair, 16 rows).
// ============================================================
template<int K, bool L1>
__global__ void __launch_bounds__(384, 1) k_xw(const float* __restrict__ in,
                                               const float* __restrict__ W,
                                               const float* __restrict__ bias) {
    extern __shared__ __align__(16) char smraw[];
    ulonglong2* Wp = (ulonglong2*)smraw;                       // [K/2][192]
    float* xs0 = (float*)(smraw + (size_t)(K / 2) * 192 * 16); // buf0 [32][K]
    float* xs1 = xs0 + 32 * K;                                 // buf1 [32][K]
    int tid = threadIdx.x;
    int cp = tid % 192, rg = tid / 192;
    int rbase = rg * 16;
    const float* base = L1 ? in : (const float*)g_seq1;

    for (int i = tid; i < (K / 2) * 192; i += 384) {
        int j = i / 192, c2 = i % 192;
        const float* w0 = W + (size_t)(2 * j) * C3 + 2 * c2;
        Wp[i] = make_ulonglong2(pack2(w0[0], w0[C3]), pack2(w0[1], w0[C3 + 1]));
    }
    float2 bq = *(const float2*)&bias[2 * cp];
    __syncthreads();

    constexpr int NV = 32 * K / 4;
    int ch = blockIdx.x;
    if (ch < 8192) {
        const float4* src = (const float4*)(base + (size_t)ch * 32 * K);
        for (int i = tid; i < NV; i += 384) cpa16(&xs0[i * 4], &src[i]);
    }
    cpa_commit();
    int buf = 0;

    for (; ch < 8192; ch += gridDim.x) {
        float* cur = buf ? xs1 : xs0;
        float* nxtb = buf ? xs0 : xs1;
        cpa_wait0();
        __syncthreads();
        int nch = ch + gridDim.x;
        if (nch < 8192) {
            const float4* src = (const float4*)(base + (size_t)nch * 32 * K);
            for (int i = tid; i < NV; i += 384) cpa16(&nxtb[i * 4], &src[i]);
        }
        cpa_commit();

        ull acc0[16], acc1[16];
#pragma unroll
        for (int r = 0; r < 16; r++) { acc0[r] = 0; acc1[r] = 0; }
        for (int kq = 0; kq < K / 4; kq++) {
            ulonglong2 wA = Wp[(2 * kq) * 192 + cp];
            ulonglong2 wB = Wp[(2 * kq + 1) * 192 + cp];
            const float* xrow = cur + (size_t)rbase * K + 4 * kq;
#pragma unroll
            for (int r = 0; r < 16; r++) {
                ulonglong2 x4 = *(const ulonglong2*)(xrow + (size_t)r * K);
                acc0[r] = ffma2(x4.x, wA.x, acc0[r]);
                acc1[r] = ffma2(x4.x, wA.y, acc1[r]);
                acc0[r] = ffma2(x4.y, wB.x, acc0[r]);
                acc1[r] = ffma2(x4.y, wB.y, acc1[r]);
            }
        }
#pragma unroll
        for (int r = 0; r < 16; r++) {
            float2 v0 = up2(acc0[r]), v1 = up2(acc1[r]);
            int rr = ch * 32 + rbase + r;
            int orow = L1 ? ((rr & 1023) * 256 + (rr >> 10)) : rr;
            float2 o = make_float2(v0.x + v0.y + bq.x, v1.x + v1.y + bq.y);
            *(float2*)&g_xw[(size_t)orow * C3 + 2 * cp] = o;
        }
        buf ^= 1;
    }
}

// ============================================================
// k_gru v5: batch-staggered pipeline. 1 CTA = 2 batch rows, 384 threads.
// Per step two phases; each phase = gates(batch b) || recurrent-dot(batch 1-b).
// Gate MUFU chain hides under the other batch's dot issue stream.
// Weights register-resident (64 packed k-pairs). 2 barriers/step (unchanged).
// ============================================================
template<bool WSEQ>
__global__ void __launch_bounds__(384, 1) k_gru(const float* __restrict__ Uw,
                                                const float* __restrict__ br,
                                                float* __restrict__ stateOut,
                                                float* __restrict__ xOut) {
    __shared__ __align__(16) float h2[2][128];   // per-batch hidden state
    __shared__ float recs[2][C3];                // per-batch recurrent pre-act
    int c = threadIdx.x, p = blockIdx.x;
    ull wp[64];
#pragma unroll
    for (int j = 0; j < 64; j++)
        wp[j] = pack2(Uw[(size_t)(2 * j) * C3 + c], Uw[(size_t)(2 * j + 1) * C3 + c]);
    float brc = br[c];
    if (c < 128) { h2[0][c] = 0.f; h2[1][c] = 0.f; }
    recs[0][c] = brc;                      // rec0(0): h=0 -> just recurrent bias
    bool gat = c < 128;
    int u = c;                             // gate threads own unit u (both batches)
    const float* xq0 = g_xw + (size_t)(2 * p) * C3 + u;
    const float* xq1 = g_xw + (size_t)(2 * p + 1) * C3 + u;
    float* sq0 = g_seq1 + (size_t)(2 * p) * 128 + u;
    float* sq1 = g_seq1 + (size_t)(2 * p + 1) * 128 + u;
    bool pf = gat && ((u & 31) == 0);
    float hv0 = 0.f, hv1 = 0.f;
    float xz = 0.f, xr = 0.f, xh = 0.f;
    if (gat) { xz = xq0[0]; xr = xq0[128]; xh = xq0[256]; }   // (b0, t0)
    __syncthreads();

    for (int t = 0; t < 1024; t++) {
        // ---- phase A: gates batch0 (t) || dot over h1 -> rec1(t) ----
        {
            ull ae = 0ull, ao = 0ull;
#pragma unroll
            for (int j = 0; j < 32; j++) {
                ulonglong2 q = *(const ulonglong2*)&h2[1][4 * j];
                ae = ffma2(q.x, wp[2 * j], ae);
                ao = ffma2(q.y, wp[2 * j + 1], ao);
            }
            if (gat) {
                float z  = sigm(xz + recs[0][u]);
                float r  = sigm(xr + recs[0][u + 128]);
                float hh = fmaxf(xh + r * recs[0][u + 256], 0.f);
                hv0 = z * hv0 + (1.f - z) * hh;
                h2[0][u] = hv0;
                if (WSEQ) sq0[(size_t)t * (256 * 128)] = hv0;
                const float* q1 = xq1 + (size_t)t * (256 * C3);   // prefetch (b1, t)
                xz = q1[0]; xr = q1[128]; xh = q1[256];
            }
            if (pf && t < 1023) {   // warm L2 for batch0 t+1
                const float* q = xq0 + (size_t)(t + 1) * (256 * C3);
                pfL2(q); pfL2(q + 128); pfL2(q + 256);
            }
            float2 ve = up2(ae), vo = up2(ao);
            recs[1][c] = (ve.x + ve.y) + (vo.x + vo.y) + brc;
        }
        __syncthreads();
        // ---- phase B: gates batch1 (t) || dot over h0(t) -> rec0(t+1) ----
        {
            ull ae = 0ull, ao = 0ull;
#pragma unroll
            for (int j = 0; j < 32; j++) {
                ulonglong2 q = *(const ulonglong2*)&h2[0][4 * j];
                ae = ffma2(q.x, wp[2 * j], ae);
                ao = ffma2(q.y, wp[2 * j + 1], ao);
            }
            if (gat) {
                float z  = sigm(xz + recs[1][u]);
                float r  = sigm(xr + recs[1][u + 128]);
                float hh = fmaxf(xh + r * recs[1][u + 256], 0.f);
                hv1 = z * hv1 + (1.f - z) * hh;
                h2[1][u] = hv1;
                if (WSEQ) sq1[(size_t)t * (256 * 128)] = hv1;
                if (t < 1023) {
                    const float* q0 = xq0 + (size_t)(t + 1) * (256 * C3);  // prefetch (b0, t+1)
                    xz = q0[0]; xr = q0[128]; xh = q0[256];
                }
            }
            if (pf && t < 1023) {   // warm L2 for batch1 t+1
                const float* q = xq1 + (size_t)(t + 1) * (256 * C3);
                pfL2(q); pfL2(q + 128); pfL2(q + 256);
            }
            float2 ve = up2(ae), vo = up2(ao);
            recs[0][c] = (ve.x + ve.y) + (vo.x + vo.y) + brc;
        }
        __syncthreads();
    }
    if (gat) {
        stateOut[(size_t)(2 * p) * 128 + u]     = hv0;
        stateOut[(size_t)(2 * p + 1) * 128 + u] = hv1;
        if (xOut) {
            xOut[(size_t)(2 * p) * 128 + u]     = hv0;
            xOut[(size_t)(2 * p + 1) * 128 + u] = hv1;
        }
    }
}

extern "C" void kernel_launch(void* const* d_in, const int* in_sizes, int n_in,
                              void* d_out, int out_size) {
    const float* x  = (const float*)d_in[0];
    const float* W1 = (const float*)d_in[1];
    const float* U1 = (const float*)d_in[2];
    const float* b1 = (const float*)d_in[3];
    const float* W2 = (const float*)d_in[4];
    const float* U2 = (const float*)d_in[5];
    const float* b2 = (const float*)d_in[6];
    float* out = (float*)d_out;  // [x | state1 | state2], each 256*128

    int sm1 = (64 / 2) * 192 * 16 + 2 * 32 * 64 * 4;     // 114688
    int sm2 = (128 / 2) * 192 * 16 + 2 * 32 * 128 * 4;   // 229376
    cudaFuncSetAttribute(k_xw<64, true>,   cudaFuncAttributeMaxDynamicSharedMemorySize, sm1);
    cudaFuncSetAttribute(k_xw<128, false>, cudaFuncAttributeMaxDynamicSharedMemorySize, sm2);

    k_xw<64, true><<<148, 384, sm1>>>(x, W1, b1);
    k_gru<true><<<128, 384>>>(U1, b1 + C3, out + 32768, nullptr);
    k_xw<128, false><<<148, 384, sm2>>>(nullptr, W2, b2);
    k_gru<false><<<128, 384>>>(U2, b2 + C3, out + 65536, out);
}

// round 12
// speedup vs baseline: 1.5622x; 1.5622x over previous
#include <cuda_runtime.h>
#include <cstdint>
#include <cstddef>
typedef unsigned long long ull;
#define C3 384

__device__ float g_xw[(size_t)1024 * 256 * C3];     // [t][b][384] gate pre-acts
__device__ float g_seq1[(size_t)1024 * 256 * 128];  // [t][b][128] layer-1 outputs

__device__ __forceinline__ ull ffma2(ull a, ull b, ull c) {
    ull d; asm("fma.rn.f32x2 %0,%1,%2,%3;" : "=l"(d) : "l"(a), "l"(b), "l"(c)); return d;
}
__device__ __forceinline__ ull pack2(float x, float y) {
    ull d; asm("mov.b64 %0,{%1,%2};" : "=l"(d) : "f"(x), "f"(y)); return d;
}
__device__ __forceinline__ float2 up2(ull v) {
    float x, y; asm("mov.b64 {%0,%1},%2;" : "=f"(x), "=f"(y) : "l"(v)); return make_float2(x, y);
}
__device__ __forceinline__ float sigm(float x) {   // sigmoid(x) = 0.5*tanh(0.5x)+0.5 (HW tanh)
    float t; asm("tanh.approx.f32 %0, %1;" : "=f"(t) : "f"(0.5f * x));
    return fmaf(0.5f, t, 0.5f);
}
__device__ __forceinline__ void pfL2(const void* p) {
    asm volatile("prefetch.global.L2 [%0];" :: "l"(p));
}
__device__ __forceinline__ void cpa16(void* s, const void* g) {
    uint32_t sa = (uint32_t)__cvta_generic_to_shared(s);
    asm volatile("cp.async.ca.shared.global [%0], [%1], 16;" :: "r"(sa), "l"(g));
}
__device__ __forceinline__ void cpa_commit() { asm volatile("cp.async.commit_group;"); }
__device__ __forceinline__ void cpa_wait0() { asm volatile("cp.async.wait_group 0;"); }

// ============================================================
// k_xw v6: cp.async double-buffered, 32-row chunks,
// thread = (col-quad cq: 4 cols, rowgroup rg: 8 rows). acc = 32 ull = 64 regs.
// Each broadcast x-LDS.128 feeds 8 ffma2 -> LDS stream ~= fma stream.
// ============================================================
template<int K, bool L1>
__global__ void __launch_bounds__(384, 1) k_xw(const float* __restrict__ in,
                                               const float* __restrict__ W,
                                               const float* __restrict__ bias) {
    extern __shared__ __align__(16) char smraw[];
    ulonglong2* Wp = (ulonglong2*)smraw;                       // [K/2][192]
    float* xs0 = (float*)(smraw + (size_t)(K / 2) * 192 * 16); // buf0 [32][K]
    float* xs1 = xs0 + 32 * K;                                 // buf1 [32][K]
    int tid = threadIdx.x;
    int cq = tid % 96, rg = tid / 96;
    int rbase = rg * 8;
    const float* base = L1 ? in : (const float*)g_seq1;

    // Wp[j*192+cp] = {(W[2j][2cp],W[2j+1][2cp]), (W[2j][2cp+1],W[2j+1][2cp+1])}
    for (int i = tid; i < (K / 2) * 192; i += 384) {
        int j = i / 192, c2 = i % 192;
        const float* w0 = W + (size_t)(2 * j) * C3 + 2 * c2;
        Wp[i] = make_ulonglong2(pack2(w0[0], w0[C3]), pack2(w0[1], w0[C3 + 1]));
    }
    float4 bq = *(const float4*)&bias[4 * cq];
    __syncthreads();

    constexpr int NV = 32 * K / 4;
    int ch = blockIdx.x;
    if (ch < 8192) {
        const float4* src = (const float4*)(base + (size_t)ch * 32 * K);
        for (int i = tid; i < NV; i += 384) cpa16(&xs0[i * 4], &src[i]);
    }
    cpa_commit();
    int buf = 0;

    for (; ch < 8192; ch += gridDim.x) {
        float* cur = buf ? xs1 : xs0;
        float* nxtb = buf ? xs0 : xs1;
        cpa_wait0();
        __syncthreads();
        int nch = ch + gridDim.x;
        if (nch < 8192) {
            const float4* src = (const float4*)(base + (size_t)nch * 32 * K);
            for (int i = tid; i < NV; i += 384) cpa16(&nxtb[i * 4], &src[i]);
        }
        cpa_commit();

        ull acc0[8], acc1[8], acc2[8], acc3[8];
#pragma unroll
        for (int r = 0; r < 8; r++) { acc0[r] = 0; acc1[r] = 0; acc2[r] = 0; acc3[r] = 0; }

        for (int kq = 0; kq < K / 4; kq++) {
            ulonglong2 wA0 = Wp[(2 * kq) * 192 + 2 * cq];
            ulonglong2 wA1 = Wp[(2 * kq) * 192 + 2 * cq + 1];
            ulonglong2 wB0 = Wp[(2 * kq + 1) * 192 + 2 * cq];
            ulonglong2 wB1 = Wp[(2 * kq + 1) * 192 + 2 * cq + 1];
            const float* xrow = cur + (size_t)rbase * K + 4 * kq;
#pragma unroll
            for (int r = 0; r < 8; r++) {
                ulonglong2 x4 = *(const ulonglong2*)(xrow + (size_t)r * K);  // broadcast
                acc0[r] = ffma2(x4.x, wA0.x, acc0[r]);
                acc1[r] = ffma2(x4.x, wA0.y, acc1[r]);
                acc2[r] = ffma2(x4.x, wA1.x, acc2[r]);
                acc3[r] = ffma2(x4.x, wA1.y, acc3[r]);
                acc0[r] = ffma2(x4.y, wB0.x, acc0[r]);
                acc1[r] = ffma2(x4.y, wB0.y, acc1[r]);
                acc2[r] = ffma2(x4.y, wB1.x, acc2[r]);
                acc3[r] = ffma2(x4.y, wB1.y, acc3[r]);
            }
        }

#pragma unroll
        for (int r = 0; r < 8; r++) {
            float2 v0 = up2(acc0[r]), v1 = up2(acc1[r]);
            float2 v2 = up2(acc2[r]), v3 = up2(acc3[r]);
            int rr = ch * 32 + rbase + r;
            int orow = L1 ? ((rr & 1023) * 256 + (rr >> 10)) : rr;
            float4 o = make_float4(v0.x + v0.y + bq.x, v1.x + v1.y + bq.y,
                                   v2.x + v2.y + bq.z, v3.x + v3.y + bq.w);
            *(float4*)&g_xw[(size_t)orow * C3 + 4 * cq] = o;
        }
        buf ^= 1;
    }
}

// ============================================================
// k_gru v3 + tanh sigmoid: 1 CTA = 2 batch rows; 384 threads = cols.
// Interleaved h; recurrent weights register-resident (64 packed k-pairs).
// ============================================================
template<bool WSEQ>
__global__ void __launch_bounds__(384, 1) k_gru(const float* __restrict__ Uw,
                                                const float* __restrict__ br,
                                                float* __restrict__ stateOut,
                                                float* __restrict__ xOut) {
    __shared__ __align__(16) float hsi[256];
    __shared__ __align__(8) float2 rss[C3];
    int c = threadIdx.x, p = blockIdx.x;
    ull wp[64];
#pragma unroll
    for (int j = 0; j < 64; j++)
        wp[j] = pack2(Uw[(size_t)(2 * j) * C3 + c], Uw[(size_t)(2 * j + 1) * C3 + c]);
    float brc = br[c];
    if (c < 256) hsi[c] = 0.f;
    int u = c & 127, bl = (c >> 7) & 1;
    bool g = c < 256;
    int b = 2 * p + bl;
    int hidx = 4 * (u >> 1) + 2 * bl + (u & 1);
    const float* xq = g_xw + (size_t)b * C3 + u;
    float* sq = g_seq1 + (size_t)b * 128 + u;
    bool pf = g && ((u & 31) == 0);
    float hval = 0.f;
    __syncthreads();
    for (int t = 0; t < 1024; t++) {
        float xz = 0.f, xr = 0.f, xh = 0.f;
        if (g) {
            const float* q = xq + (size_t)t * (256 * C3);
            xz = q[0]; xr = q[128]; xh = q[256];
        }
        if (pf && t < 1023) {
            const float* q = xq + (size_t)(t + 1) * (256 * C3);
            pfL2(q); pfL2(q + 128); pfL2(q + 256);
        }
        ull a0 = 0ull, a1 = 0ull;
#pragma unroll
        for (int j = 0; j < 64; j++) {
            ulonglong2 q = *(const ulonglong2*)&hsi[4 * j];
            a0 = ffma2(q.x, wp[j], a0);
            a1 = ffma2(q.y, wp[j], a1);
        }
        float2 v0 = up2(a0), v1 = up2(a1);
        rss[c] = make_float2(v0.x + v0.y + brc, v1.x + v1.y + brc);
        __syncthreads();
        if (g) {
            float2 rz = rss[u], rr2 = rss[u + 128], rh = rss[u + 256];
            float z  = sigm(xz + (bl ? rz.y : rz.x));
            float r  = sigm(xr + (bl ? rr2.y : rr2.x));
            float hh = fmaxf(xh + r * (bl ? rh.y : rh.x), 0.f);
            float hn = z * hval + (1.f - z) * hh;
            hval = hn;
            hsi[hidx] = hn;
            if (WSEQ) sq[(size_t)t * (256 * 128)] = hn;
            if (t == 1023) {
                stateOut[(size_t)b * 128 + u] = hn;
                if (xOut) xOut[(size_t)b * 128 + u] = hn;
            }
        }
        __syncthreads();
    }
}

extern "C" void kernel_launch(void* const* d_in, const int* in_sizes, int n_in,
                              void* d_out, int out_size) {
    const float* x  = (const float*)d_in[0];
    const float* W1 = (const float*)d_in[1];
    const float* U1 = (const float*)d_in[2];
    const float* b1 = (const float*)d_in[3];
    const float* W2 = (const float*)d_in[4];
    const float* U2 = (const float*)d_in[5];
    const float* b2 = (const float*)d_in[6];
    float* out = (float*)d_out;  // [x | state1 | state2], each 256*128

    int sm1 = (64 / 2) * 192 * 16 + 2 * 32 * 64 * 4;     // 114688
    int sm2 = (128 / 2) * 192 * 16 + 2 * 32 * 128 * 4;   // 229376
    cudaFuncSetAttribute(k_xw<64, true>,   cudaFuncAttributeMaxDynamicSharedMemorySize, sm1);
    cudaFuncSetAttribute(k_xw<128, false>, cudaFuncAttributeMaxDynamicSharedMemorySize, sm2);

    k_xw<64, true><<<148, 384, sm1>>>(x, W1, b1);
    k_gru<true><<<128, 384>>>(U1, b1 + C3, out + 32768, nullptr);
    k_xw<128, false><<<148, 384, sm2>>>(nullptr, W2, b2);
    k_gru<false><<<128, 384>>>(U2, b2 + C3, out + 65536, out);
}

// round 13
// speedup vs baseline: 1.6004x; 1.0245x over previous
#include <cuda_runtime.h>
#include <cstdint>
#include <cstddef>
typedef unsigned long long ull;
#define C3 384

__device__ float g_xw[(size_t)1024 * 256 * C3];     // [t][b][384] gate pre-acts
__device__ float g_seq1[(size_t)1024 * 256 * 128];  // [t][b][128] layer-1 outputs

__device__ __forceinline__ ull ffma2(ull a, ull b, ull c) {
    ull d; asm("fma.rn.f32x2 %0,%1,%2,%3;" : "=l"(d) : "l"(a), "l"(b), "l"(c)); return d;
}
__device__ __forceinline__ ull pack2(float x, float y) {
    ull d; asm("mov.b64 %0,{%1,%2};" : "=l"(d) : "f"(x), "f"(y)); return d;
}
__device__ __forceinline__ float2 up2(ull v) {
    float x, y; asm("mov.b64 {%0,%1},%2;" : "=f"(x), "=f"(y) : "l"(v)); return make_float2(x, y);
}
__device__ __forceinline__ float sigm(float x) {   // sigmoid via HW tanh
    float t; asm("tanh.approx.f32 %0, %1;" : "=f"(t) : "f"(0.5f * x));
    return fmaf(0.5f, t, 0.5f);
}
__device__ __forceinline__ void pfL2(const void* p) {
    asm volatile("prefetch.global.L2 [%0];" :: "l"(p));
}
__device__ __forceinline__ void cpa16(void* s, const void* g) {
    uint32_t sa = (uint32_t)__cvta_generic_to_shared(s);
    asm volatile("cp.async.ca.shared.global [%0], [%1], 16;" :: "r"(sa), "l"(g));
}
__device__ __forceinline__ void cpa_commit() { asm volatile("cp.async.commit_group;"); }
__device__ __forceinline__ void cpa_wait0() { asm volatile("cp.async.wait_group 0;"); }

// ============================================================
// k_xw v7: cp.async double-buffered, 32-row chunks,
// thread = (col-quad cq: 4 cols, rowgroup rg: 8 rows). acc = 32 ull.
// Weight smem layout [j][s][cq] -> every w-LDS.128 is 16B lane stride (4 wf).
// ============================================================
template<int K, bool L1>
__global__ void __launch_bounds__(384, 1) k_xw(const float* __restrict__ in,
                                               const float* __restrict__ W,
                                               const float* __restrict__ bias) {
    extern __shared__ __align__(16) char smraw[];
    ulonglong2* Wq = (ulonglong2*)smraw;                       // [K/2][2][96]
    float* xs0 = (float*)(smraw + (size_t)(K / 2) * 192 * 16); // buf0 [32][K]
    float* xs1 = xs0 + 32 * K;                                 // buf1 [32][K]
    int tid = threadIdx.x;
    int cq = tid % 96, rg = tid / 96;
    int rbase = rg * 8;
    const float* base = L1 ? in : (const float*)g_seq1;

    // Wq[j*192 + s*96 + cq] = k-pair j, cols (4cq+2s, 4cq+2s+1):
    //   (pack2(W[2j][c0],W[2j+1][c0]), pack2(W[2j][c0+1],W[2j+1][c0+1]))
    for (int i = tid; i < (K / 2) * 192; i += 384) {
        int j = i / 192, r = i % 192;
        int s = r / 96, c2 = r % 96;
        int c0 = 4 * c2 + 2 * s;
        const float* w0 = W + (size_t)(2 * j) * C3 + c0;
        Wq[i] = make_ulonglong2(pack2(w0[0], w0[C3]), pack2(w0[1], w0[C3 + 1]));
    }
    float4 bq = *(const float4*)&bias[4 * cq];
    __syncthreads();

    constexpr int NV = 32 * K / 4;
    int ch = blockIdx.x;
    if (ch < 8192) {
        const float4* src = (const float4*)(base + (size_t)ch * 32 * K);
        for (int i = tid; i < NV; i += 384) cpa16(&xs0[i * 4], &src[i]);
    }
    cpa_commit();
    int buf = 0;

    for (; ch < 8192; ch += gridDim.x) {
        float* cur = buf ? xs1 : xs0;
        float* nxtb = buf ? xs0 : xs1;
        cpa_wait0();
        __syncthreads();
        int nch = ch + gridDim.x;
        if (nch < 8192) {
            const float4* src = (const float4*)(base + (size_t)nch * 32 * K);
            for (int i = tid; i < NV; i += 384) cpa16(&nxtb[i * 4], &src[i]);
        }
        cpa_commit();

        ull acc0[8], acc1[8], acc2[8], acc3[8];
#pragma unroll
        for (int r = 0; r < 8; r++) { acc0[r] = 0; acc1[r] = 0; acc2[r] = 0; acc3[r] = 0; }

        for (int kq = 0; kq < K / 4; kq++) {
            int j0 = 2 * kq, j1 = 2 * kq + 1;
            ulonglong2 wA0 = Wq[j0 * 192 + cq];        // k-pair j0, cols 4cq,4cq+1  (4 wf)
            ulonglong2 wA1 = Wq[j0 * 192 + 96 + cq];   // k-pair j0, cols 4cq+2,4cq+3
            ulonglong2 wB0 = Wq[j1 * 192 + cq];        // k-pair j1, cols 4cq,4cq+1
            ulonglong2 wB1 = Wq[j1 * 192 + 96 + cq];
            const float* xrow = cur + (size_t)rbase * K + 4 * kq;
#pragma unroll
            for (int r = 0; r < 8; r++) {
                ulonglong2 x4 = *(const ulonglong2*)(xrow + (size_t)r * K);  // broadcast
                acc0[r] = ffma2(x4.x, wA0.x, acc0[r]);
                acc1[r] = ffma2(x4.x, wA0.y, acc1[r]);
                acc2[r] = ffma2(x4.x, wA1.x, acc2[r]);
                acc3[r] = ffma2(x4.x, wA1.y, acc3[r]);
                acc0[r] = ffma2(x4.y, wB0.x, acc0[r]);
                acc1[r] = ffma2(x4.y, wB0.y, acc1[r]);
                acc2[r] = ffma2(x4.y, wB1.x, acc2[r]);
                acc3[r] = ffma2(x4.y, wB1.y, acc3[r]);
            }
        }

#pragma unroll
        for (int r = 0; r < 8; r++) {
            float2 v0 = up2(acc0[r]), v1 = up2(acc1[r]);
            float2 v2 = up2(acc2[r]), v3 = up2(acc3[r]);
            int rr = ch * 32 + rbase + r;
            int orow = L1 ? ((rr & 1023) * 256 + (rr >> 10)) : rr;
            float4 o = make_float4(v0.x + v0.y + bq.x, v1.x + v1.y + bq.y,
                                   v2.x + v2.y + bq.z, v3.x + v3.y + bq.w);
            *(float4*)&g_xw[(size_t)orow * C3 + 4 * cq] = o;
        }
        buf ^= 1;
    }
}

// ============================================================
// k_gru (frozen, R12): 1 CTA = 2 batch rows; 384 threads = cols.
// Interleaved h; recurrent weights register-resident (64 packed k-pairs).
// ============================================================
template<bool WSEQ>
__global__ void __launch_bounds__(384, 1) k_gru(const float* __restrict__ Uw,
                                                const float* __restrict__ br,
                                                float* __restrict__ stateOut,
                                                float* __restrict__ xOut) {
    __shared__ __align__(16) float hsi[256];
    __shared__ __align__(8) float2 rss[C3];
    int c = threadIdx.x, p = blockIdx.x;
    ull wp[64];
#pragma unroll
    for (int j = 0; j < 64; j++)
        wp[j] = pack2(Uw[(size_t)(2 * j) * C3 + c], Uw[(size_t)(2 * j + 1) * C3 + c]);
    float brc = br[c];
    if (c < 256) hsi[c] = 0.f;
    int u = c & 127, bl = (c >> 7) & 1;
    bool g = c < 256;
    int b = 2 * p + bl;
    int hidx = 4 * (u >> 1) + 2 * bl + (u & 1);
    const float* xq = g_xw + (size_t)b * C3 + u;
    float* sq = g_seq1 + (size_t)b * 128 + u;
    bool pf = g && ((u & 31) == 0);
    float hval = 0.f;
    __syncthreads();
    for (int t = 0; t < 1024; t++) {
        float xz = 0.f, xr = 0.f, xh = 0.f;
        if (g) {
            const float* q = xq + (size_t)t * (256 * C3);
            xz = q[0]; xr = q[128]; xh = q[256];
        }
        if (pf && t < 1023) {
            const float* q = xq + (size_t)(t + 1) * (256 * C3);
            pfL2(q); pfL2(q + 128); pfL2(q + 256);
        }
        ull a0 = 0ull, a1 = 0ull;
#pragma unroll
        for (int j = 0; j < 64; j++) {
            ulonglong2 q = *(const ulonglong2*)&hsi[4 * j];
            a0 = ffma2(q.x, wp[j], a0);
            a1 = ffma2(q.y, wp[j], a1);
        }
        float2 v0 = up2(a0), v1 = up2(a1);
        rss[c] = make_float2(v0.x + v0.y + brc, v1.x + v1.y + brc);
        __syncthreads();
        if (g) {
            float2 rz = rss[u], rr2 = rss[u + 128], rh = rss[u + 256];
            float z  = sigm(xz + (bl ? rz.y : rz.x));
            float r  = sigm(xr + (bl ? rr2.y : rr2.x));
            float hh = fmaxf(xh + r * (bl ? rh.y : rh.x), 0.f);
            float hn = z * hval + (1.f - z) * hh;
            hval = hn;
            hsi[hidx] = hn;
            if (WSEQ) sq[(size_t)t * (256 * 128)] = hn;
            if (t == 1023) {
                stateOut[(size_t)b * 128 + u] = hn;
                if (xOut) xOut[(size_t)b * 128 + u] = hn;
            }
        }
        __syncthreads();
    }
}

extern "C" void kernel_launch(void* const* d_in, const int* in_sizes, int n_in,
                              void* d_out, int out_size) {
    const float* x  = (const float*)d_in[0];
    const float* W1 = (const float*)d_in[1];
    const float* U1 = (const float*)d_in[2];
    const float* b1 = (const float*)d_in[3];
    const float* W2 = (const float*)d_in[4];
    const float* U2 = (const float*)d_in[5];
    const float* b2 = (const float*)d_in[6];
    float* out = (float*)d_out;  // [x | state1 | state2], each 256*128

    int sm1 = (64 / 2) * 192 * 16 + 2 * 32 * 64 * 4;     // 114688
    int sm2 = (128 / 2) * 192 * 16 + 2 * 32 * 128 * 4;   // 229376
    cudaFuncSetAttribute(k_xw<64, true>,   cudaFuncAttributeMaxDynamicSharedMemorySize, sm1);
    cudaFuncSetAttribute(k_xw<128, false>, cudaFuncAttributeMaxDynamicSharedMemorySize, sm2);

    k_xw<64, true><<<148, 384, sm1>>>(x, W1, b1);
    k_gru<true><<<128, 384>>>(U1, b1 + C3, out + 32768, nullptr);
    k_xw<128, false><<<148, 384, sm2>>>(nullptr, W2, b2);
    k_gru<false><<<128, 384>>>(U2, b2 + C3, out + 65536, out);
}

// round 15
// speedup vs baseline: 1.6916x; 1.0570x over previous
#include <cuda_runtime.h>
#include <cuda_bf16.h>
#include <cstdint>
#include <cstddef>
typedef unsigned long long ull;
#define C3 384

__device__ float g_xw[(size_t)1024 * 256 * C3];     // [t][b][384] gate pre-acts
__device__ float g_seq1[(size_t)1024 * 256 * 128];  // [t][b][128] layer-1 outputs

// ---------------- scalar helpers ----------------
__device__ __forceinline__ ull ffma2(ull a, ull b, ull c) {
    ull d; asm("fma.rn.f32x2 %0,%1,%2,%3;" : "=l"(d) : "l"(a), "l"(b), "l"(c)); return d;
}
__device__ __forceinline__ ull pack2(float x, float y) {
    ull d; asm("mov.b64 %0,{%1,%2};" : "=l"(d) : "f"(x), "f"(y)); return d;
}
__device__ __forceinline__ float2 up2(ull v) {
    float x, y; asm("mov.b64 {%0,%1},%2;" : "=f"(x), "=f"(y) : "l"(v)); return make_float2(x, y);
}
__device__ __forceinline__ float sigm(float x) {   // sigmoid via HW tanh
    float t; asm("tanh.approx.f32 %0, %1;" : "=f"(t) : "f"(0.5f * x));
    return fmaf(0.5f, t, 0.5f);
}
__device__ __forceinline__ void pfL2(const void* p) {
    asm volatile("prefetch.global.L2 [%0];" :: "l"(p));
}
// packed bf16 pair: lo-half = bf16(e), hi-half = bf16(o)
__device__ __forceinline__ uint32_t bfpair_hi(float e, float o) {
    uint32_t d; asm("cvt.rn.bf16x2.f32 %0, %1, %2;" : "=r"(d) : "f"(o), "f"(e)); return d;
}
__device__ __forceinline__ uint32_t bfpair_lo(float e, float o, uint32_t hp) {
    float he = __uint_as_float(hp << 16);
    float ho = __uint_as_float(hp & 0xFFFF0000u);
    uint32_t d; asm("cvt.rn.bf16x2.f32 %0, %1, %2;" : "=r"(d) : "f"(o - ho), "f"(e - he)); return d;
}
__device__ __forceinline__ void mma16816(float* c, const uint32_t* a, const uint32_t* b) {
    asm volatile(
        "mma.sync.aligned.m16n8k16.row.col.f32.bf16.bf16.f32 "
        "{%0,%1,%2,%3}, {%4,%5,%6,%7}, {%8,%9}, {%0,%1,%2,%3};"
        : "+f"(c[0]), "+f"(c[1]), "+f"(c[2]), "+f"(c[3])
        : "r"(a[0]), "r"(a[1]), "r"(a[2]), "r"(a[3]), "r"(b[0]), "r"(b[1]));
}

// ============================================================
// k_xw_mma: out[orow][c] = sum_k in[row][k]*W[k][c] + bias[c]
// via mma.sync m16n8k16 bf16-split-2 (3 terms, fp32 accum).
// 148 persistent CTAs, 74 per N-half (192 cols). CTA tile 64 rows x 192.
// 12 warps = 2(m) x 6(n); warp tile 32x32 (2 m-tiles x 4 n-tiles).
// W staged once in B-fragment order; x staged per tile in A-fragment
// order (hi+lo), double-buffered.
// ============================================================
template<int K, bool L1>
__global__ void __launch_bounds__(384, 1)
k_xw_mma(const float* __restrict__ in, const float* __restrict__ W,
         const float* __restrict__ bias) {
    constexpr int S = K / 16;                  // k16 steps
    constexpr int NB = S * 1536;               // b32 per B-half (S*24*32*2)
    constexpr int NA = S * 512;                // b32 per A-half per buffer
    extern __shared__ __align__(16) uint32_t smw[];
    uint32_t* Bh = smw;                        // [S][24][32][2]
    uint32_t* Bl = Bh + NB;
    uint32_t* Af = Bl + NB;                    // 2 buffers x (hi NA + lo NA)

    int tid = threadIdx.x, lane = tid & 31, w = tid >> 5;
    int g = lane >> 2, tg = lane & 3;
    int warp_m = w / 6, warp_n = w % 6;
    int bid = blockIdx.x;
    int nhalf = bid >= 74 ? 1 : 0;
    int n0 = nhalf * 192;
    const float* base = L1 ? in : (const float*)g_seq1;

    // ---- stage B fragments once (hi+lo) ----
    for (int i = tid; i < S * 768; i += 384) {   // (s, nt, t)
        int t = i & 31, nt = (i >> 5) % 24, s = i / 768;
        int gg = t >> 2, tt = t & 3;
        int col = n0 + nt * 8 + gg;
        int k = s * 16 + 2 * tt;
        float w00 = W[(size_t)k * C3 + col],       w01 = W[(size_t)(k + 1) * C3 + col];
        float w10 = W[(size_t)(k + 8) * C3 + col], w11 = W[(size_t)(k + 9) * C3 + col];
        uint32_t h0 = bfpair_hi(w00, w01), h1 = bfpair_hi(w10, w11);
        int idx = ((s * 24 + nt) * 32 + t) * 2;
        *(uint2*)&Bh[idx] = make_uint2(h0, h1);
        *(uint2*)&Bl[idx] = make_uint2(bfpair_lo(w00, w01, h0), bfpair_lo(w10, w11, h1));
    }

    // bias regs for this thread's columns
    float2 bv[4];
#pragma unroll
    for (int ntl = 0; ntl < 4; ntl++)
        bv[ntl] = *(const float2*)&bias[n0 + warp_n * 32 + ntl * 8 + 2 * tg];

    // ---- A staging lambda (fragment order, hi+lo) ----
    auto stageA = [&](int rt, uint32_t* A) {
        for (int i = tid; i < S * 128; i += 384) {   // (s, mt, t)
            int t = i & 31, mt = (i >> 5) & 3, s = i >> 7;
            int gg = t >> 2, tt = t & 3;
            int row0 = rt * 64 + mt * 16 + gg;
            const float* rp0 = base + (size_t)row0 * K + s * 16 + 2 * tt;
            const float* rp1 = rp0 + 8 * K;
            float2 v00 = *(const float2*)rp0;         // (g,   k)
            float2 v10 = *(const float2*)rp1;         // (g+8, k)
            float2 v01 = *(const float2*)(rp0 + 8);   // (g,   k+8)
            float2 v11 = *(const float2*)(rp1 + 8);   // (g+8, k+8)
            uint32_t h0 = bfpair_hi(v00.x, v00.y), h1 = bfpair_hi(v10.x, v10.y);
            uint32_t h2 = bfpair_hi(v01.x, v01.y), h3 = bfpair_hi(v11.x, v11.y);
            int idx = ((s * 4 + mt) * 32 + t) * 4;
            *(uint4*)&A[idx] = make_uint4(h0, h1, h2, h3);
            *(uint4*)&A[NA + idx] = make_uint4(
                bfpair_lo(v00.x, v00.y, h0), bfpair_lo(v10.x, v10.y, h1),
                bfpair_lo(v01.x, v01.y, h2), bfpair_lo(v11.x, v11.y, h3));
        }
    };

    int rt = nhalf ? bid - 74 : bid;
    stageA(rt, Af);               // prologue into buffer 0
    __syncthreads();
    int buf = 0;

    for (; rt < 4096; rt += 74) {
        const uint32_t* Ab = Af + buf * 2 * NA;
        float acc[2][4][4];
#pragma unroll
        for (int m = 0; m < 2; m++)
#pragma unroll
            for (int n = 0; n < 4; n++)
#pragma unroll
                for (int q = 0; q < 4; q++) acc[m][n][q] = 0.f;

#pragma unroll
        for (int term = 0; term < 3; term++) {
            const uint32_t* A = Ab + (term == 1 ? NA : 0);
            const uint32_t* B = (term == 2) ? Bl : Bh;
#pragma unroll
            for (int s = 0; s < S; s++) {
                uint4 af[2];
#pragma unroll
                for (int m = 0; m < 2; m++)
                    af[m] = *(const uint4*)&A[((s * 4 + warp_m * 2 + m) * 32 + lane) * 4];
                uint2 bf[4];
#pragma unroll
                for (int n = 0; n < 4; n++)
                    bf[n] = *(const uint2*)&B[((s * 24 + warp_n * 4 + n) * 32 + lane) * 2];
#pragma unroll
                for (int m = 0; m < 2; m++)
#pragma unroll
                    for (int n = 0; n < 4; n++)
                        mma16816(acc[m][n], (const uint32_t*)&af[m], (const uint32_t*)&bf[n]);
            }
        }

        // stage next tile into the other buffer (overlaps epilogue below)
        int nrt = rt + 74;
        if (nrt < 4096) stageA(nrt, Af + (buf ^ 1) * 2 * NA);

        // epilogue: acc -> g_xw with bias and (L1) transpose
#pragma unroll
        for (int m = 0; m < 2; m++) {
            int rin = rt * 64 + warp_m * 32 + m * 16 + g;
            int r2 = rin + 8;
            int o1 = L1 ? ((rin & 1023) * 256 + (rin >> 10)) : rin;
            int o2 = L1 ? ((r2 & 1023) * 256 + (r2 >> 10)) : r2;
#pragma unroll
            for (int n = 0; n < 4; n++) {
                int co = n0 + warp_n * 32 + n * 8 + 2 * tg;
                *(float2*)&g_xw[(size_t)o1 * C3 + co] =
                    make_float2(acc[m][n][0] + bv[n].x, acc[m][n][1] + bv[n].y);
                *(float2*)&g_xw[(size_t)o2 * C3 + co] =
                    make_float2(acc[m][n][2] + bv[n].x, acc[m][n][3] + bv[n].y);
            }
        }
        __syncthreads();
        buf ^= 1;
    }
}

// ============================================================
// k_gru (frozen, R13): 1 CTA = 2 batch rows; 384 threads = cols.
// Interleaved h; recurrent weights register-resident (64 packed k-pairs).
// ============================================================
template<bool WSEQ>
__global__ void __launch_bounds__(384, 1) k_gru(const float* __restrict__ Uw,
                                                const float* __restrict__ br,
                                                float* __restrict__ stateOut,
                                                float* __restrict__ xOut) {
    __shared__ __align__(16) float hsi[256];
    __shared__ __align__(8) float2 rss[C3];
    int c = threadIdx.x, p = blockIdx.x;
    ull wp[64];
#pragma unroll
    for (int j = 0; j < 64; j++)
        wp[j] = pack2(Uw[(size_t)(2 * j) * C3 + c], Uw[(size_t)(2 * j + 1) * C3 + c]);
    float brc = br[c];
    if (c < 256) hsi[c] = 0.f;
    int u = c & 127, bl = (c >> 7) & 1;
    bool g = c < 256;
    int b = 2 * p + bl;
    int hidx = 4 * (u >> 1) + 2 * bl + (u & 1);
    const float* xq = g_xw + (size_t)b * C3 + u;
    float* sq = g_seq1 + (size_t)b * 128 + u;
    bool pf = g && ((u & 31) == 0);
    float hval = 0.f;
    __syncthreads();
    for (int t = 0; t < 1024; t++) {
        float xz = 0.f, xr = 0.f, xh = 0.f;
        if (g) {
            const float* q = xq + (size_t)t * (256 * C3);
            xz = q[0]; xr = q[128]; xh = q[256];
        }
        if (pf && t < 1023) {
            const float* q = xq + (size_t)(t + 1) * (256 * C3);
            pfL2(q); pfL2(q + 128); pfL2(q + 256);
        }
        ull a0 = 0ull, a1 = 0ull;
#pragma unroll
        for (int j = 0; j < 64; j++) {
            ulonglong2 q = *(const ulonglong2*)&hsi[4 * j];
            a0 = ffma2(q.x, wp[j], a0);
            a1 = ffma2(q.y, wp[j], a1);
        }
        float2 v0 = up2(a0), v1 = up2(a1);
        rss[c] = make_float2(v0.x + v0.y + brc, v1.x + v1.y + brc);
        __syncthreads();
        if (g) {
            float2 rz = rss[u], rr2 = rss[u + 128], rh = rss[u + 256];
            float z  = sigm(xz + (bl ? rz.y : rz.x));
            float r  = sigm(xr + (bl ? rr2.y : rr2.x));
            float hh = fmaxf(xh + r * (bl ? rh.y : rh.x), 0.f);
            float hn = z * hval + (1.f - z) * hh;
            hval = hn;
            hsi[hidx] = hn;
            if (WSEQ) sq[(size_t)t * (256 * 128)] = hn;
            if (t == 1023) {
                stateOut[(size_t)b * 128 + u] = hn;
                if (xOut) xOut[(size_t)b * 128 + u] = hn;
            }
        }
        __syncthreads();
    }
}

extern "C" void kernel_launch(void* const* d_in, const int* in_sizes, int n_in,
                              void* d_out, int out_size) {
    const float* x  = (const float*)d_in[0];
    const float* W1 = (const float*)d_in[1];
    const float* U1 = (const float*)d_in[2];
    const float* b1 = (const float*)d_in[3];
    const float* W2 = (const float*)d_in[4];
    const float* U2 = (const float*)d_in[5];
    const float* b2 = (const float*)d_in[6];
    float* out = (float*)d_out;  // [x | state1 | state2], each 256*128

    // smem bytes: S*(1536*2 + 2048) b32 * 4  = 20480*S
    int sm1 = 20480 * (64 / 16);     // 81920
    int sm2 = 20480 * (128 / 16);    // 163840
    cudaFuncSetAttribute(k_xw_mma<64, true>,   cudaFuncAttributeMaxDynamicSharedMemorySize, sm1);
    cudaFuncSetAttribute(k_xw_mma<128, false>, cudaFuncAttributeMaxDynamicSharedMemorySize, sm2);

    k_xw_mma<64, true><<<148, 384, sm1>>>(x, W1, b1);
    k_gru<true><<<128, 384>>>(U1, b1 + C3, out + 32768, nullptr);
    k_xw_mma<128, false><<<148, 384, sm2>>>(nullptr, W2, b2);
    k_gru<false><<<128, 384>>>(U2, b2 + C3, out + 65536, out);
}